// round 4
// baseline (speedup 1.0000x reference)
#include <cuda_runtime.h>
#include <cstdint>
#include <cstddef>

// Problem constants
#define NB 4
#define NH 8
#define ND 64
#define NE 512
#define NR 512
#define NC 512

typedef unsigned long long u64;

// ---- packed f32x2 helpers (sm_103a FFMA2 — PTX-only, ptxas won't auto-fuse) ----
__device__ __forceinline__ u64 pack2(float lo, float hi) {
    u64 r; asm("mov.b64 %0, {%1, %2};" : "=l"(r) : "f"(lo), "f"(hi)); return r;
}
__device__ __forceinline__ void unpack2(u64 v, float& lo, float& hi) {
    asm("mov.b64 {%0, %1}, %2;" : "=f"(lo), "=f"(hi) : "l"(v));
}
__device__ __forceinline__ void ffma2(u64& d, u64 a, u64 b) {
    asm("fma.rn.f32x2 %0, %1, %2, %0;" : "+l"(d) : "l"(a), "l"(b));
}
__device__ __forceinline__ u64 fmul2(u64 a, u64 b) {
    u64 r; asm("mul.rn.f32x2 %0, %1, %2;" : "=l"(r) : "l"(a), "l"(b)); return r;
}
__device__ __forceinline__ u64 fadd2(u64 a, u64 b) {
    u64 r; asm("add.rn.f32x2 %0, %1, %2;" : "=l"(r) : "l"(a), "l"(b)); return r;
}
__device__ __forceinline__ u64 relu2(u64 v) {
    float lo, hi; unpack2(v, lo, hi);
    return pack2(fmaxf(lo, 0.0f), fmaxf(hi, 0.0f));
}

// Scratch (device globals; allocation inside kernel_launch is forbidden)
__device__ float g_Q[NB * NR * NE];
__device__ float g_K[NB * NC * NE];
__device__ float g_V[NB * NC * NE];
__device__ float g_logits[(size_t)NB * NH * NR * NC];  // dot -> logits -> weights (in place)
__device__ float g_attn[NB * NR * NE];
__device__ int   g_mask_is_i32;

// ---------------------------------------------------------------------------
// Probe mask dtype (bool-as-int32 vs uint8). Reads 256 bytes.
// ---------------------------------------------------------------------------
__global__ void detect_mask_kernel(const unsigned char* __restrict__ m)
{
    int is32 = 1;
    for (int i = 0; i < 256; i++)
        if ((i & 3) != 0 && m[i] != 0) { is32 = 0; break; }
    g_mask_is_i32 = is32;
}

// ---------------------------------------------------------------------------
// C = alpha * A * B^T, packed-f32x2 inner loop.
// A-tile in smem as duplicated {v,v} u64; B-tile as plain floats read in pairs.
// ---------------------------------------------------------------------------
__global__ __launch_bounds__(256) void sgemm_nt(
    const float* __restrict__ A, const float* __restrict__ B, float* __restrict__ C,
    int K, int lda, int ldb, int ldc,
    int inner, size_t aOut, size_t aIn, size_t bOut, size_t bIn, size_t cOut, size_t cIn,
    float alpha)
{
    int z = blockIdx.z;
    int zo = z / inner, zi = z - zo * inner;
    A += zo * aOut + zi * aIn;
    B += zo * bOut + zi * bIn;
    C += zo * cOut + zi * cIn;

    __shared__ __align__(16) u64  As2[16][66];   // duplicated pairs
    __shared__ __align__(16) float Bs[16][68];

    int tid = threadIdx.x;
    int tx = tid & 15, ty = tid >> 4;
    int tm = blockIdx.y * 64, tn = blockIdx.x * 64;

    u64 acc[4][2];
#pragma unroll
    for (int i = 0; i < 4; i++) { acc[i][0] = 0ull; acc[i][1] = 0ull; }

    int lr = tid >> 2;         // 0..63 (tile row)
    int lk = (tid & 3) << 2;   // 0,4,8,12 (k sub-offset)

    for (int k0 = 0; k0 < K; k0 += 16) {
        float4 av = *reinterpret_cast<const float4*>(A + (size_t)(tm + lr) * lda + k0 + lk);
        float4 bv = *reinterpret_cast<const float4*>(B + (size_t)(tn + lr) * ldb + k0 + lk);
        As2[lk + 0][lr] = pack2(av.x, av.x);
        As2[lk + 1][lr] = pack2(av.y, av.y);
        As2[lk + 2][lr] = pack2(av.z, av.z);
        As2[lk + 3][lr] = pack2(av.w, av.w);
        Bs[lk + 0][lr] = bv.x; Bs[lk + 1][lr] = bv.y; Bs[lk + 2][lr] = bv.z; Bs[lk + 3][lr] = bv.w;
        __syncthreads();
#pragma unroll
        for (int kk = 0; kk < 16; kk++) {
            u64 ar[4];
#pragma unroll
            for (int i = 0; i < 4; i++) ar[i] = As2[kk][ty * 4 + i];
            u64 br0 = *reinterpret_cast<const u64*>(&Bs[kk][tx * 4]);
            u64 br1 = *reinterpret_cast<const u64*>(&Bs[kk][tx * 4 + 2]);
#pragma unroll
            for (int i = 0; i < 4; i++) {
                ffma2(acc[i][0], ar[i], br0);
                ffma2(acc[i][1], ar[i], br1);
            }
        }
        __syncthreads();
    }

#pragma unroll
    for (int i = 0; i < 4; i++) {
        float a0, a1, a2, a3;
        unpack2(acc[i][0], a0, a1);
        unpack2(acc[i][1], a2, a3);
        float4 o = make_float4(alpha * a0, alpha * a1, alpha * a2, alpha * a3);
        *reinterpret_cast<float4*>(C + (size_t)(tm + ty * 4 + i) * ldc + tn + tx * 4) = o;
    }
}

// ---------------------------------------------------------------------------
// C = A * B (NN), packed-f32x2 inner loop — used for attn@V.
// ---------------------------------------------------------------------------
__global__ __launch_bounds__(256) void sgemm_nn(
    const float* __restrict__ A, const float* __restrict__ B, float* __restrict__ C,
    int K, int lda, int ldb, int ldc,
    int inner, size_t aOut, size_t aIn, size_t bOut, size_t bIn, size_t cOut, size_t cIn)
{
    int z = blockIdx.z;
    int zo = z / inner, zi = z - zo * inner;
    A += zo * aOut + zi * aIn;
    B += zo * bOut + zi * bIn;
    C += zo * cOut + zi * cIn;

    __shared__ __align__(16) u64  As2[16][66];
    __shared__ __align__(16) float Bs[16][68];

    int tid = threadIdx.x;
    int tx = tid & 15, ty = tid >> 4;
    int tm = blockIdx.y * 64, tn = blockIdx.x * 64;

    u64 acc[4][2];
#pragma unroll
    for (int i = 0; i < 4; i++) { acc[i][0] = 0ull; acc[i][1] = 0ull; }

    int lr = tid >> 2;        // A: tile row 0..63
    int lk = (tid & 3) << 2;  // A: k sub 0,4,8,12
    int kr = tid >> 4;        // B: k row 0..15
    int nb = (tid & 15) << 2; // B: n sub 0..60

    for (int k0 = 0; k0 < K; k0 += 16) {
        float4 av = *reinterpret_cast<const float4*>(A + (size_t)(tm + lr) * lda + k0 + lk);
        float4 bv = *reinterpret_cast<const float4*>(B + (size_t)(k0 + kr) * ldb + tn + nb);
        As2[lk + 0][lr] = pack2(av.x, av.x);
        As2[lk + 1][lr] = pack2(av.y, av.y);
        As2[lk + 2][lr] = pack2(av.z, av.z);
        As2[lk + 3][lr] = pack2(av.w, av.w);
        Bs[kr][nb + 0] = bv.x; Bs[kr][nb + 1] = bv.y; Bs[kr][nb + 2] = bv.z; Bs[kr][nb + 3] = bv.w;
        __syncthreads();
#pragma unroll
        for (int kk = 0; kk < 16; kk++) {
            u64 ar[4];
#pragma unroll
            for (int i = 0; i < 4; i++) ar[i] = As2[kk][ty * 4 + i];
            u64 br0 = *reinterpret_cast<const u64*>(&Bs[kk][tx * 4]);
            u64 br1 = *reinterpret_cast<const u64*>(&Bs[kk][tx * 4 + 2]);
#pragma unroll
            for (int i = 0; i < 4; i++) {
                ffma2(acc[i][0], ar[i], br0);
                ffma2(acc[i][1], ar[i], br1);
            }
        }
        __syncthreads();
    }

#pragma unroll
    for (int i = 0; i < 4; i++) {
        float a0, a1, a2, a3;
        unpack2(acc[i][0], a0, a1);
        unpack2(acc[i][1], a2, a3);
        float4 o = make_float4(a0, a1, a2, a3);
        *reinterpret_cast<float4*>(C + (size_t)(tm + ty * 4 + i) * ldc + tn + tx * 4) = o;
    }
}

// ---------------------------------------------------------------------------
// Mix MLP, packed-f32x2. Weights pre-duplicated {w,w} in smem so broadcast
// LDS.64 feeds FFMA2 directly. Columns processed as 2 pairs per thread.
//   hid_i = cost * (sum_h W1[i][2h+1]) + sum_h dot_h * W1[i][2h]; relu; @W2^T
// ---------------------------------------------------------------------------
__global__ __launch_bounds__(128) void mix_kernel(
    const float* __restrict__ cost, const float* __restrict__ W1,
    const float* __restrict__ W2, float* __restrict__ logits)
{
    __shared__ u64 w1e2[128][8];   // {w,w} even features
    __shared__ u64 w1o2[128];      // {s,s} summed odd feature
    __shared__ u64 w2s2[8][128];   // {w,w}

    int tx = threadIdx.x;
    {
        float s = 0.0f;
#pragma unroll
        for (int h = 0; h < 8; h++) {
            float w = W1[tx * 16 + 2 * h];
            w1e2[tx][h] = pack2(w, w);
            s += W1[tx * 16 + 2 * h + 1];
        }
        w1o2[tx] = pack2(s, s);
#pragma unroll
        for (int j = 0; j < 8; j++) {
            float w = W2[j * 128 + tx];
            w2s2[j][tx] = pack2(w, w);
        }
    }
    __syncthreads();

    int br = blockIdx.x;
    int b = br >> 9;
    int r = br & 511;
    int c0 = tx * 4;

    u64 dv01[8], dv23[8];
#pragma unroll
    for (int h = 0; h < 8; h++) {
        float4 t = *reinterpret_cast<const float4*>(
            logits + (((size_t)(b * NH + h) * NR + r) * NC + c0));
        dv01[h] = pack2(t.x, t.y);
        dv23[h] = pack2(t.z, t.w);
    }
    float4 cvv = *reinterpret_cast<const float4*>(cost + ((size_t)b * NR + r) * NC + c0);
    u64 cw01 = pack2(cvv.x, cvv.y);
    u64 cw23 = pack2(cvv.z, cvv.w);

    u64 ms01[8], ms23[8];
#pragma unroll
    for (int h = 0; h < 8; h++) { ms01[h] = 0ull; ms23[h] = 0ull; }

    for (int i = 0; i < 128; i++) {
        u64 wo = w1o2[i];
        // stage 1: two partial accumulators per pair -> 4 dep chains
        u64 ha01 = fmul2(cw01, wo), ha23 = fmul2(cw23, wo);
        u64 hb01 = 0ull, hb23 = 0ull;
#pragma unroll
        for (int hh = 0; hh < 4; hh++) {
            u64 w = w1e2[i][hh];
            ffma2(ha01, dv01[hh], w);
            ffma2(ha23, dv23[hh], w);
        }
#pragma unroll
        for (int hh = 4; hh < 8; hh++) {
            u64 w = w1e2[i][hh];
            ffma2(hb01, dv01[hh], w);
            ffma2(hb23, dv23[hh], w);
        }
        u64 h01 = relu2(fadd2(ha01, hb01));
        u64 h23 = relu2(fadd2(ha23, hb23));
#pragma unroll
        for (int hh = 0; hh < 8; hh++) {
            u64 w = w2s2[hh][i];
            ffma2(ms01[hh], h01, w);
            ffma2(ms23[hh], h23, w);
        }
    }

#pragma unroll
    for (int h = 0; h < 8; h++) {
        float m0, m1, m2, m3;
        unpack2(ms01[h], m0, m1);
        unpack2(ms23[h], m2, m3);
        float4 o = make_float4(m0, m1, m2, m3);
        *reinterpret_cast<float4*>(logits + (((size_t)(b * NH + h) * NR + r) * NC + c0)) = o;
    }
}

// ---------------------------------------------------------------------------
// Masked softmax over last dim (512); fully-masked rows become fully unmasked.
// Mask dtype (uint8 vs int32) selected at runtime via g_mask_is_i32.
// ---------------------------------------------------------------------------
__global__ __launch_bounds__(128) void softmax_kernel(
    float* __restrict__ logits, const void* __restrict__ maskv)
{
    int row = blockIdx.x;
    float* lg = logits + (size_t)row * NC;
    int tx = threadIdx.x;
    int lane = tx & 31, wid = tx >> 5;

    float4 v = reinterpret_cast<const float4*>(lg)[tx];

    uchar4 mk;
    if (g_mask_is_i32) {
        int4 t = reinterpret_cast<const int4*>(maskv)[(size_t)row * (NC / 4) + tx];
        mk = make_uchar4(t.x != 0, t.y != 0, t.z != 0, t.w != 0);
    } else {
        mk = reinterpret_cast<const uchar4*>(maskv)[(size_t)row * (NC / 4) + tx];
    }

    __shared__ float pmax[4];
    __shared__ float psum[4];
    __shared__ int pall[4];

    bool mine_all = (mk.x != 0) && (mk.y != 0) && (mk.z != 0) && (mk.w != 0);
    unsigned bal = __ballot_sync(0xffffffffu, mine_all);
    if (lane == 0) pall[wid] = (bal == 0xffffffffu) ? 1 : 0;
    __syncthreads();
    bool am = pall[0] && pall[1] && pall[2] && pall[3];

    const float NEG = __int_as_float(0xff800000);  // -inf
    float x0 = (!am && mk.x) ? NEG : v.x;
    float x1 = (!am && mk.y) ? NEG : v.y;
    float x2 = (!am && mk.z) ? NEG : v.z;
    float x3 = (!am && mk.w) ? NEG : v.w;

    float m = fmaxf(fmaxf(x0, x1), fmaxf(x2, x3));
#pragma unroll
    for (int s = 16; s > 0; s >>= 1) m = fmaxf(m, __shfl_xor_sync(0xffffffffu, m, s));
    if (lane == 0) pmax[wid] = m;
    __syncthreads();
    float rmax = fmaxf(fmaxf(pmax[0], pmax[1]), fmaxf(pmax[2], pmax[3]));

    float e0 = __expf(x0 - rmax);
    float e1 = __expf(x1 - rmax);
    float e2 = __expf(x2 - rmax);
    float e3 = __expf(x3 - rmax);

    float sm = (e0 + e1) + (e2 + e3);
#pragma unroll
    for (int s = 16; s > 0; s >>= 1) sm += __shfl_xor_sync(0xffffffffu, sm, s);
    if (lane == 0) psum[wid] = sm;
    __syncthreads();
    float inv = 1.0f / (((psum[0] + psum[1]) + (psum[2] + psum[3])));

    float4 o = make_float4(e0 * inv, e1 * inv, e2 * inv, e3 * inv);
    reinterpret_cast<float4*>(lg)[tx] = o;
}

// ---------------------------------------------------------------------------
extern "C" void kernel_launch(void* const* d_in, const int* in_sizes, int n_in,
                              void* d_out, int out_size)
{
    const float* row_emb = (const float*)d_in[0];
    const float* col_emb = (const float*)d_in[1];
    const float* cost    = (const float*)d_in[2];
    const void*  mask    = d_in[3];
    const float* Wq      = (const float*)d_in[4];
    const float* Wk      = (const float*)d_in[5];
    const float* Wv      = (const float*)d_in[6];
    const float* Wmix1   = (const float*)d_in[7];
    const float* Wmix2   = (const float*)d_in[8];
    const float* Wout    = (const float*)d_in[9];
    float* out = (float*)d_out;

    float *Q, *K, *V, *L, *AT;
    cudaGetSymbolAddress((void**)&Q,  g_Q);
    cudaGetSymbolAddress((void**)&K,  g_K);
    cudaGetSymbolAddress((void**)&V,  g_V);
    cudaGetSymbolAddress((void**)&L,  g_logits);
    cudaGetSymbolAddress((void**)&AT, g_attn);

    const size_t RE = (size_t)NR * NE;      // 262144
    const size_t RC = (size_t)NR * NC;      // 262144

    detect_mask_kernel<<<1, 1>>>((const unsigned char*)mask);

    // Q/K/V projections: [2048,512] = emb @ W^T
    sgemm_nt<<<dim3(NE / 64, (NB * NR) / 64, 1), 256>>>(
        row_emb, Wq, Q, NE, NE, NE, NE,
        1, 0, 0, 0, 0, 0, 0, 1.0f);
    sgemm_nt<<<dim3(NE / 64, (NB * NC) / 64, 1), 256>>>(
        col_emb, Wk, K, NE, NE, NE, NE,
        1, 0, 0, 0, 0, 0, 0, 1.0f);
    sgemm_nt<<<dim3(NE / 64, (NB * NC) / 64, 1), 256>>>(
        col_emb, Wv, V, NE, NE, NE, NE,
        1, 0, 0, 0, 0, 0, 0, 1.0f);

    // dot[b,h,r,c] = (1/8) * q . k   (batched over z = b*8+h)
    sgemm_nt<<<dim3(NC / 64, NR / 64, NB * NH), 256>>>(
        Q, K, L, ND, NE, NE, NC,
        NH, RE, (size_t)ND, RE, (size_t)ND, (size_t)NH * RC, RC,
        0.125f);

    // mix MLP (in place on L)
    mix_kernel<<<NB * NR, 128>>>(cost, Wmix1, Wmix2, L);

    // masked softmax (in place on L)
    softmax_kernel<<<NB * NH * NR, 128>>>(L, mask);

    // attn @ V -> g_attn[b, r, h*64+d]
    sgemm_nn<<<dim3(1, NR / 64, NB * NH), 256>>>(
        L, V, AT, NC, NC, NE, NE,
        NH, (size_t)NH * RC, RC, (size_t)NC * NE, (size_t)ND, RE, (size_t)ND);

    // final projection: out = attn @ Wout^T
    sgemm_nt<<<dim3(NE / 64, (NB * NR) / 64, 1), 256>>>(
        AT, Wout, out, NE, NE, NE, NE,
        1, 0, 0, 0, 0, 0, 0, 1.0f);
}